// round 2
// baseline (speedup 1.0000x reference)
#include <cuda_runtime.h>
#include <cuda_bf16.h>

// Problem constants
#define T_TYPES 27
#define N_NODES 16384
#define B_BATCH 256
#define IN_DIM  300
#define HID     128
#define OUT_DIM 64

// Scratch for pooled means [T, B, IN_DIM]
__device__ float g_pooled[T_TYPES * B_BATCH * IN_DIM];

__device__ __forceinline__ int lower_bound_i32(const int* s, int n, int v) {
    int lo = 0, hi = n;
    while (lo < hi) {
        int mid = (lo + hi) >> 1;
        if (s[mid] < v) lo = mid + 1; else hi = mid;
    }
    return lo;
}

// ---------------------------------------------------------------------------
// Kernel 1: segment mean pooling.
// grid = (B_BATCH, T_TYPES), block = 128 threads.
// Each block handles one (t, b) segment: binary-search the contiguous row
// range in the sorted segment_ids (int32!), then coalesced-stream the rows.
// ---------------------------------------------------------------------------
__global__ void pool_kernel(const float* __restrict__ feat,
                            const int* __restrict__ seg) {
    const int b = blockIdx.x;
    const int t = blockIdx.y;
    const int tid = threadIdx.x;

    const int* s = seg + (size_t)t * N_NODES;

    __shared__ int s_bounds[2];
    if (tid == 0) s_bounds[0] = lower_bound_i32(s, N_NODES, b);
    if (tid == 1) s_bounds[1] = lower_bound_i32(s, N_NODES, b + 1);
    __syncthreads();

    const int lo = s_bounds[0];
    const int hi = s_bounds[1];
    const int cnt = hi - lo;

    float a0 = 0.f, a1 = 0.f, a2 = 0.f;
    const int c = tid;                       // column 0..127
    const bool has3 = (c + 256) < IN_DIM;    // c < 44

    const float* fb = feat + ((size_t)t * N_NODES + lo) * IN_DIM;
    #pragma unroll 4
    for (int r = 0; r < cnt; ++r) {
        a0 += fb[c];
        a1 += fb[c + 128];
        if (has3) a2 += fb[c + 256];
        fb += IN_DIM;
    }

    const float inv = 1.0f / (float)max(cnt, 1);
    float* po = g_pooled + ((size_t)t * B_BATCH + b) * IN_DIM;
    po[c]       = a0 * inv;
    po[c + 128] = a1 * inv;
    if (has3) po[c + 256] = a2 * inv;
}

// ---------------------------------------------------------------------------
// Kernel 2: per-type 2-layer MLP + transpose.
// grid = (B/32, T), block = 128 threads. Each block computes a 32-row tile of
// one type: h = relu(pooled @ W1 + b1); out = h @ W2 + b2 -> out[b, t, o].
// ---------------------------------------------------------------------------
#define ROWS 32
#define SP_STRIDE 304   // padded row stride (floats), 16B-aligned

__global__ __launch_bounds__(128, 4)
void mlp_kernel(const float* __restrict__ W1,
                const float* __restrict__ b1,
                const float* __restrict__ W2,
                const float* __restrict__ b2,
                float* __restrict__ out) {
    const int t  = blockIdx.y;
    const int b0 = blockIdx.x * ROWS;
    const int tid = threadIdx.x;

    __shared__ float smem[ROWS * SP_STRIDE];   // 38912 B

    // ---- load pooled tile [32 x 300] (contiguous gmem -> padded smem) ----
    {
        const float* src = g_pooled + ((size_t)t * B_BATCH + b0) * IN_DIM;
        for (int idx = tid; idx < ROWS * IN_DIM; idx += 128) {
            int br = idx / IN_DIM;
            int k  = idx - br * IN_DIM;
            smem[br * SP_STRIDE + k] = src[idx];
        }
    }
    __syncthreads();

    // ---- GEMM1: h[b][j] = relu(sum_k sp[b][k] * W1[t][k][j] + b1[t][j]) ----
    const int j = tid;  // 0..127
    float acc[ROWS];
    {
        const float bj = b1[t * HID + j];
        #pragma unroll
        for (int b = 0; b < ROWS; ++b) acc[b] = bj;

        const float* w1p = W1 + (size_t)t * IN_DIM * HID + j;
        for (int k = 0; k < IN_DIM; k += 4) {
            float w0 = w1p[(k + 0) * HID];
            float w1 = w1p[(k + 1) * HID];
            float w2 = w1p[(k + 2) * HID];
            float w3 = w1p[(k + 3) * HID];
            #pragma unroll
            for (int b = 0; b < ROWS; ++b) {
                float4 v = *(const float4*)&smem[b * SP_STRIDE + k];
                acc[b] += v.x * w0 + v.y * w1 + v.z * w2 + v.w * w3;
            }
        }
    }
    __syncthreads();   // done reading sp; reuse smem for h

    // h tile [32 x 128], row stride 128 (16B-aligned)
    float* hs = smem;
    #pragma unroll
    for (int b = 0; b < ROWS; ++b)
        hs[b * HID + j] = fmaxf(acc[b], 0.f);
    __syncthreads();

    // ---- GEMM2: out[b][o] = sum_j h[b][j] * W2[t][j][o] + b2[t][o] ----
    const int o  = tid & 63;        // 0..63
    const int bh = tid >> 6;        // 0..1 -> rows bh*16 .. bh*16+15
    float acc2[16];
    {
        const float bo = b2[t * OUT_DIM + o];
        #pragma unroll
        for (int b = 0; b < 16; ++b) acc2[b] = bo;

        const float* w2p = W2 + (size_t)t * HID * OUT_DIM + o;
        for (int jj = 0; jj < HID; jj += 4) {
            float w0 = w2p[(jj + 0) * OUT_DIM];
            float w1 = w2p[(jj + 1) * OUT_DIM];
            float w2v = w2p[(jj + 2) * OUT_DIM];
            float w3 = w2p[(jj + 3) * OUT_DIM];
            #pragma unroll
            for (int b = 0; b < 16; ++b) {
                float4 v = *(const float4*)&hs[(bh * 16 + b) * HID + jj];
                acc2[b] += v.x * w0 + v.y * w1 + v.z * w2v + v.w * w3;
            }
        }
    }

    // out layout: [B, T, OUT]
    #pragma unroll
    for (int b = 0; b < 16; ++b) {
        int brow = b0 + bh * 16 + b;
        out[((size_t)brow * T_TYPES + t) * OUT_DIM + o] = acc2[b];
    }
}

// ---------------------------------------------------------------------------
extern "C" void kernel_launch(void* const* d_in, const int* in_sizes, int n_in,
                              void* d_out, int out_size) {
    const float* feat = (const float*)d_in[0];
    const int*   seg  = (const int*)d_in[1];
    const float* W1   = (const float*)d_in[2];
    const float* b1   = (const float*)d_in[3];
    const float* W2   = (const float*)d_in[4];
    const float* b2   = (const float*)d_in[5];
    float* out = (float*)d_out;

    dim3 pgrid(B_BATCH, T_TYPES);
    pool_kernel<<<pgrid, 128>>>(feat, seg);

    dim3 mgrid(B_BATCH / ROWS, T_TYPES);
    mlp_kernel<<<mgrid, 128>>>(W1, b1, W2, b2, out);
}

// round 3
// speedup vs baseline: 1.3847x; 1.3847x over previous
#include <cuda_runtime.h>
#include <cuda_bf16.h>

// Problem constants
#define T_TYPES 27
#define N_NODES 16384
#define B_BATCH 256
#define IN_DIM  300
#define HID     128
#define OUT_DIM 64

// Scratch for pooled means [T, B, IN_DIM] (row-major, contiguous 300 per row)
__device__ __align__(16) float g_pooled[T_TYPES * B_BATCH * IN_DIM];

typedef unsigned long long ull;

__device__ __forceinline__ ull fma2(ull a, ull b, ull c) {
    ull d;
    asm("fma.rn.f32x2 %0, %1, %2, %3;" : "=l"(d) : "l"(a), "l"(b), "l"(c));
    return d;
}
__device__ __forceinline__ ull pack2(float x) {
    ull d; asm("mov.b64 %0, {%1, %1};" : "=l"(d) : "f"(x)); return d;
}
__device__ __forceinline__ void unpack2(ull v, float& lo, float& hi) {
    asm("mov.b64 {%0, %1}, %2;" : "=f"(lo), "=f"(hi) : "l"(v));
}

__device__ __forceinline__ int lower_bound_i32(const int* s, int n, int v) {
    int lo = 0, hi = n;
    while (lo < hi) {
        int mid = (lo + hi) >> 1;
        if (s[mid] < v) lo = mid + 1; else hi = mid;
    }
    return lo;
}

// ---------------------------------------------------------------------------
// Kernel 1: segment mean pooling. grid=(B,T), block=64.
// Row = 300 floats = 75 float4. Threads 0..63 take float4 col tid; threads
// 0..10 additionally take col 64+tid. Streaming __ldcs loads.
// ---------------------------------------------------------------------------
__global__ void pool_kernel(const float* __restrict__ feat,
                            const int* __restrict__ seg) {
    const int b = blockIdx.x;
    const int t = blockIdx.y;
    const int tid = threadIdx.x;

    const int* s = seg + (size_t)t * N_NODES;
    __shared__ int s_bounds[2];
    if (tid < 2) s_bounds[tid] = lower_bound_i32(s, N_NODES, b + tid);
    __syncthreads();

    const int lo = s_bounds[0];
    const int cnt = s_bounds[1] - lo;

    float4 aA = make_float4(0.f, 0.f, 0.f, 0.f);
    float4 aB = make_float4(0.f, 0.f, 0.f, 0.f);
    const bool hasB = tid < 11;

    const float4* fb = (const float4*)(feat + ((size_t)t * N_NODES + lo) * IN_DIM);
    #pragma unroll 4
    for (int r = 0; r < cnt; ++r) {
        float4 v = __ldcs(&fb[tid]);
        aA.x += v.x; aA.y += v.y; aA.z += v.z; aA.w += v.w;
        if (hasB) {
            float4 w = __ldcs(&fb[64 + tid]);
            aB.x += w.x; aB.y += w.y; aB.z += w.z; aB.w += w.w;
        }
        fb += 75;
    }

    const float inv = 1.0f / (float)max(cnt, 1);
    float4* po = (float4*)(g_pooled + ((size_t)t * B_BATCH + b) * IN_DIM);
    po[tid] = make_float4(aA.x * inv, aA.y * inv, aA.z * inv, aA.w * inv);
    if (hasB)
        po[64 + tid] = make_float4(aB.x * inv, aB.y * inv, aB.z * inv, aB.w * inv);
}

// ---------------------------------------------------------------------------
// Kernel 2: per-type 2-layer MLP + transpose, f32x2 packed math.
// grid = (B/16, T) = (16, 27) = 432 blocks, 128 threads.
// Batch rows packed in pairs (f32x2); transposed smem tiles feed packed
// operands directly from LDS.128 broadcasts.
// ---------------------------------------------------------------------------
#define ROWS 16

__global__ __launch_bounds__(128, 3)
void mlp_kernel(const float* __restrict__ W1,
                const float* __restrict__ b1,
                const float* __restrict__ W2,
                const float* __restrict__ b2,
                float* __restrict__ out) {
    const int t   = blockIdx.y;
    const int b0  = blockIdx.x * ROWS;
    const int tid = threadIdx.x;

    __shared__ float spt[IN_DIM * ROWS];  // [k][b] transposed, 19200 B
    __shared__ float ht[HID * ROWS];      // [j][b] transposed,  8192 B

    // ---- load pooled tile [16 x 300] transposed into spt[k][b] ----
    {
        const float* src = g_pooled + ((size_t)t * B_BATCH + b0) * IN_DIM;
        for (int idx = tid; idx < ROWS * IN_DIM; idx += 128) {
            int b = idx / IN_DIM;
            int k = idx - b * IN_DIM;
            spt[k * ROWS + b] = src[idx];
        }
    }
    __syncthreads();

    // ---- GEMM1: h[b][j] = relu(sum_k sp[b][k]*W1[k][j] + b1[j]), j = tid ----
    const int j = tid;
    ull acc[8];
    {
        ull binit = pack2(b1[t * HID + j]);
        #pragma unroll
        for (int p = 0; p < 8; ++p) acc[p] = binit;

        const float* w1p = W1 + (size_t)t * IN_DIM * HID + j;

        // double-buffered weight groups of 4 k's
        float w0 = w1p[0 * HID], w1 = w1p[1 * HID], w2 = w1p[2 * HID], w3 = w1p[3 * HID];
        for (int kg = 0; kg < IN_DIM / 4; ++kg) {
            const int k = kg * 4;
            float n0 = 0.f, n1 = 0.f, n2 = 0.f, n3 = 0.f;
            if (kg + 1 < IN_DIM / 4) {
                const float* wn = w1p + (k + 4) * HID;
                n0 = wn[0 * HID]; n1 = wn[1 * HID]; n2 = wn[2 * HID]; n3 = wn[3 * HID];
            }
            #pragma unroll
            for (int q = 0; q < 4; ++q) {
                float wq = (q == 0) ? w0 : (q == 1) ? w1 : (q == 2) ? w2 : w3;
                ull wp = pack2(wq);
                const ulonglong2* sp = (const ulonglong2*)&spt[(k + q) * ROWS];
                ulonglong2 s0 = sp[0];
                ulonglong2 s1 = sp[1];
                ulonglong2 s2 = sp[2];
                ulonglong2 s3 = sp[3];
                acc[0] = fma2(wp, s0.x, acc[0]);
                acc[1] = fma2(wp, s0.y, acc[1]);
                acc[2] = fma2(wp, s1.x, acc[2]);
                acc[3] = fma2(wp, s1.y, acc[3]);
                acc[4] = fma2(wp, s2.x, acc[4]);
                acc[5] = fma2(wp, s2.y, acc[5]);
                acc[6] = fma2(wp, s3.x, acc[6]);
                acc[7] = fma2(wp, s3.y, acc[7]);
            }
            w0 = n0; w1 = n1; w2 = n2; w3 = n3;
        }
    }

    // relu + transposed store: ht[j][b]
    #pragma unroll
    for (int p = 0; p < 8; ++p) {
        float lo, hi;
        unpack2(acc[p], lo, hi);
        float2 v = make_float2(fmaxf(lo, 0.f), fmaxf(hi, 0.f));
        *(float2*)&ht[j * ROWS + 2 * p] = v;
    }
    __syncthreads();

    // ---- GEMM2: out[b][o] = sum_j h[b][j]*W2[j][o] + b2[o] ----
    const int o  = tid & 63;
    const int rh = tid >> 6;                 // rows rh*8 .. rh*8+7 (4 pairs)
    ull acc2[4];
    {
        ull binit = pack2(b2[t * OUT_DIM + o]);
        #pragma unroll
        for (int p = 0; p < 4; ++p) acc2[p] = binit;

        const float* w2p = W2 + (size_t)t * HID * OUT_DIM + o;
        float w0 = w2p[0 * OUT_DIM], w1 = w2p[1 * OUT_DIM],
              w2 = w2p[2 * OUT_DIM], w3 = w2p[3 * OUT_DIM];
        for (int jg = 0; jg < HID / 4; ++jg) {
            const int jj = jg * 4;
            float n0 = 0.f, n1 = 0.f, n2 = 0.f, n3 = 0.f;
            if (jg + 1 < HID / 4) {
                const float* wn = w2p + (jj + 4) * OUT_DIM;
                n0 = wn[0 * OUT_DIM]; n1 = wn[1 * OUT_DIM];
                n2 = wn[2 * OUT_DIM]; n3 = wn[3 * OUT_DIM];
            }
            #pragma unroll
            for (int q = 0; q < 4; ++q) {
                float wq = (q == 0) ? w0 : (q == 1) ? w1 : (q == 2) ? w2 : w3;
                ull wp = pack2(wq);
                const ulonglong2* hp =
                    (const ulonglong2*)&ht[(jj + q) * ROWS + rh * 8];
                ulonglong2 h01 = hp[0];
                ulonglong2 h23 = hp[1];
                acc2[0] = fma2(wp, h01.x, acc2[0]);
                acc2[1] = fma2(wp, h01.y, acc2[1]);
                acc2[2] = fma2(wp, h23.x, acc2[2]);
                acc2[3] = fma2(wp, h23.y, acc2[3]);
            }
            w0 = n0; w1 = n1; w2 = n2; w3 = n3;
        }
    }

    // out layout: [B, T, OUT]
    #pragma unroll
    for (int p = 0; p < 4; ++p) {
        float lo, hi;
        unpack2(acc2[p], lo, hi);
        int r0 = b0 + rh * 8 + 2 * p;
        out[((size_t)r0 * T_TYPES + t) * OUT_DIM + o] = lo;
        out[((size_t)(r0 + 1) * T_TYPES + t) * OUT_DIM + o] = hi;
    }
}

// ---------------------------------------------------------------------------
extern "C" void kernel_launch(void* const* d_in, const int* in_sizes, int n_in,
                              void* d_out, int out_size) {
    const float* feat = (const float*)d_in[0];
    const int*   seg  = (const int*)d_in[1];
    const float* W1   = (const float*)d_in[2];
    const float* b1   = (const float*)d_in[3];
    const float* W2   = (const float*)d_in[4];
    const float* b2   = (const float*)d_in[5];
    float* out = (float*)d_out;

    dim3 pgrid(B_BATCH, T_TYPES);
    pool_kernel<<<pgrid, 64>>>(feat, seg);

    dim3 mgrid(B_BATCH / ROWS, T_TYPES);
    mlp_kernel<<<mgrid, 128>>>(W1, b1, W2, b2, out);
}